// round 16
// baseline (speedup 1.0000x reference)
#include <cuda_runtime.h>
#include <cuda_bf16.h>
#include <stdint.h>
#include <math.h>

#define N_NODES 100000
#define N_EDGES 500000

// Scratch (allocation-free rule: __device__ globals)
__device__ float g_Q[(size_t)N_NODES * 128];
__device__ float g_K[(size_t)N_NODES * 128];
__device__ float g_V[(size_t)N_NODES * 128];
__device__ float g_ACC[(size_t)N_NODES * 128];  // unnormalized message sums
__device__ float g_D[(size_t)N_NODES * 4];      // softmax denominators

#define PSTR 136   // proj smem row stride (bf16): 17x16B -> conflict-free LDSM
#define ESTR 72    // edge smem row stride (bf16): 9x16B  -> conflict-free LDSM

// Pre-converted weights (hi/lo bf16, pre-padded to smem strides)
__device__ __align__(16) __nv_bfloat16 g_Whi[4][128 * PSTR];
__device__ __align__(16) __nv_bfloat16 g_Wlo[4][128 * PSTR];
__device__ __align__(16) __nv_bfloat16 g_WEhi[128 * ESTR];
__device__ __align__(16) __nv_bfloat16 g_WElo[128 * ESTR];

// ---------------------------------------------------------------------------
// Portable tensor-core primitives (sm_80+; safe under the sm_103 family target)
// ---------------------------------------------------------------------------
__device__ __forceinline__ uint32_t smem_u32(const void* p) {
    uint32_t a;
    asm("{ .reg .u64 t; cvta.to.shared.u64 t, %1; cvt.u32.u64 %0, t; }"
        : "=r"(a) : "l"(p));
    return a;
}
#define LDSM4(r, addr) \
    asm volatile("ldmatrix.sync.aligned.m8n8.x4.shared.b16 {%0,%1,%2,%3}, [%4];" \
                 : "=r"((r)[0]), "=r"((r)[1]), "=r"((r)[2]), "=r"((r)[3]) \
                 : "r"(addr))
#define MMA_BF16(d, a, b0, b1) \
    asm volatile("mma.sync.aligned.m16n8k16.row.col.f32.bf16.bf16.f32 " \
                 "{%0,%1,%2,%3},{%4,%5,%6,%7},{%8,%9},{%0,%1,%2,%3};" \
                 : "+f"((d)[0]), "+f"((d)[1]), "+f"((d)[2]), "+f"((d)[3]) \
                 : "r"((a)[0]), "r"((a)[1]), "r"((a)[2]), "r"((a)[3]), \
                   "r"(b0), "r"(b1))

// ---------------------------------------------------------------------------
// fp32 -> bf16 hi/lo split into padded row-major smem (STR bf16 per row).
// ---------------------------------------------------------------------------
template <int ROWS, int KC, int STR>
__device__ __forceinline__ void cvt_tile(const float* __restrict__ src, int rows_valid,
                                         char* hi, char* lo, int tid) {
    const int QUADS = ROWS * (KC / 4);
    for (int t = tid; t < QUADS; t += 256) {
        int r = t / (KC / 4);
        int c = (t % (KC / 4)) * 4;
        float4 v = make_float4(0.f, 0.f, 0.f, 0.f);
        if (r < rows_valid) v = *(const float4*)(src + (size_t)r * KC + c);
        __nv_bfloat16 h0 = __float2bfloat16(v.x), h1 = __float2bfloat16(v.y);
        __nv_bfloat16 h2 = __float2bfloat16(v.z), h3 = __float2bfloat16(v.w);
        __nv_bfloat16 l0 = __float2bfloat16(v.x - __bfloat162float(h0));
        __nv_bfloat16 l1 = __float2bfloat16(v.y - __bfloat162float(h1));
        __nv_bfloat16 l2 = __float2bfloat16(v.z - __bfloat162float(h2));
        __nv_bfloat16 l3 = __float2bfloat16(v.w - __bfloat162float(h3));
        uint32_t off = (uint32_t)(r * STR + c) * 2;
        __nv_bfloat162 p;
        p.x = h0; p.y = h1; *(__nv_bfloat162*)(hi + off)     = p;
        p.x = h2; p.y = h3; *(__nv_bfloat162*)(hi + off + 4) = p;
        p.x = l0; p.y = l1; *(__nv_bfloat162*)(lo + off)     = p;
        p.x = l2; p.y = l3; *(__nv_bfloat162*)(lo + off + 4) = p;
    }
}

// ---------------------------------------------------------------------------
// Kernel 0: zero accumulators + one-time weight conversion (single launch)
// ---------------------------------------------------------------------------
__global__ void k_init(const float* __restrict__ Wq, const float* __restrict__ Wk,
                       const float* __restrict__ Wv, const float* __restrict__ Wsk,
                       const float* __restrict__ We) {
    int i = blockIdx.x * blockDim.x + threadIdx.x;
    if (i < N_NODES * 32) ((float4*)g_ACC)[i] = make_float4(0.f, 0.f, 0.f, 0.f);
    if (i < N_NODES)      ((float4*)g_D)[i]   = make_float4(0.f, 0.f, 0.f, 0.f);
    if (i < 4 * 16384) {
        int w = i >> 14, j = i & 16383, r = j >> 7, k = j & 127;
        const float* W = (w == 0) ? Wq : (w == 1) ? Wk : (w == 2) ? Wv : Wsk;
        float v = W[j];
        __nv_bfloat16 h = __float2bfloat16(v);
        __nv_bfloat16 l = __float2bfloat16(v - __bfloat162float(h));
        g_Whi[w][r * PSTR + k] = h;
        g_Wlo[w][r * PSTR + k] = l;
    } else if (i < 4 * 16384 + 8192) {
        int j = i - 4 * 16384, r = j >> 6, k = j & 63;
        float v = We[j];
        __nv_bfloat16 h = __float2bfloat16(v);
        __nv_bfloat16 l = __float2bfloat16(v - __bfloat162float(h));
        g_WEhi[r * ESTR + k] = h;
        g_WElo[r * ESTR + k] = l;
    }
}

// ---------------------------------------------------------------------------
// Kernel 1: node projections Q/K/V/skip. 64-row tile (2 CTAs/SM), 8 warps,
// each warp 32x32 via m16n8k16 bf16 HMMA. Fully-merged mainloop: all four
// fragment sets loaded once per k-step (8 LDSM4), 24 MMAs per step.
// ---------------------------------------------------------------------------
#define PJ_AT (64 * PSTR * 2)           // 17408 B
#define PJ_BT (128 * PSTR * 2)          // 34816 B
#define PJ_SMEM (2 * PJ_AT + 2 * PJ_BT) // 104448 B -> 2 CTAs/SM

__global__ void __launch_bounds__(256, 2) k_proj(
    const float* __restrict__ x,
    const float* __restrict__ bq, const float* __restrict__ bk,
    const float* __restrict__ bv, const float* __restrict__ bsk,
    float* __restrict__ out)
{
    extern __shared__ char sm[];
    char* AHI = sm;                     char* ALO = sm + PJ_AT;
    char* BHI = sm + 2 * PJ_AT;         char* BLO = sm + 2 * PJ_AT + PJ_BT;
    const uint32_t sAhi = smem_u32(AHI), sAlo = smem_u32(ALO);
    const uint32_t sBhi = smem_u32(BHI), sBlo = smem_u32(BLO);
    float* es = (float*)(sm + 2 * PJ_AT);  // [64][132] fp32 spill, aliases B

    const int tid = threadIdx.x, wid = tid >> 5, lane = tid & 31;
    const int row0 = blockIdx.x * 64;
    const int wr = (wid & 1) * 32, wc = (wid >> 1) * 32;

    const int grp = lane >> 3;
    const int lr  = ((grp & 1) << 3) + (lane & 7);
    const int lk  = (grp >> 1) << 3;

    cvt_tile<64, 128, PSTR>(x + (size_t)row0 * 128, N_NODES - row0, AHI, ALO, tid);

    const float* Bptr[4] = {bq, bk, bv, bsk};
    float*       Dptr[4] = {g_Q, g_K, g_V, out};

    for (int w = 0; w < 4; w++) {
        {
            const uint4* shi = (const uint4*)&g_Whi[w][0];
            const uint4* slo = (const uint4*)&g_Wlo[w][0];
            uint4* dhi = (uint4*)BHI;
            uint4* dlo = (uint4*)BLO;
            for (int t = tid; t < PJ_BT / 16; t += 256) {
                dhi[t] = shi[t];
                dlo[t] = slo[t];
            }
        }
        __syncthreads();

        float acc[2][4][4];
#pragma unroll
        for (int mi = 0; mi < 2; mi++)
#pragma unroll
            for (int nj = 0; nj < 4; nj++)
#pragma unroll
                for (int q = 0; q < 4; q++) acc[mi][nj][q] = 0.f;

        // Merged mainloop: 8 LDSM4 per k-step, 24 MMAs
#pragma unroll
        for (int k = 0; k < 128; k += 16) {
            uint32_t ah[2][4], al[2][4], bh[2][4], bl[2][4];
#pragma unroll
            for (int mi = 0; mi < 2; mi++) {
                LDSM4(ah[mi], sAhi + ((wr + mi * 16 + lr) * PSTR + k + lk) * 2);
                LDSM4(al[mi], sAlo + ((wr + mi * 16 + lr) * PSTR + k + lk) * 2);
            }
#pragma unroll
            for (int nt = 0; nt < 2; nt++) {
                LDSM4(bh[nt], sBhi + ((wc + nt * 16 + lr) * PSTR + k + lk) * 2);
                LDSM4(bl[nt], sBlo + ((wc + nt * 16 + lr) * PSTR + k + lk) * 2);
            }
#pragma unroll
            for (int mi = 0; mi < 2; mi++)
#pragma unroll
                for (int nt = 0; nt < 2; nt++) {
                    MMA_BF16(acc[mi][nt * 2 + 0], ah[mi], bh[nt][0], bh[nt][2]);
                    MMA_BF16(acc[mi][nt * 2 + 1], ah[mi], bh[nt][1], bh[nt][3]);
                    MMA_BF16(acc[mi][nt * 2 + 0], ah[mi], bl[nt][0], bl[nt][2]);
                    MMA_BF16(acc[mi][nt * 2 + 1], ah[mi], bl[nt][1], bl[nt][3]);
                    MMA_BF16(acc[mi][nt * 2 + 0], al[mi], bh[nt][0], bh[nt][2]);
                    MMA_BF16(acc[mi][nt * 2 + 1], al[mi], bh[nt][1], bh[nt][3]);
                }
        }
        __syncthreads();   // B reads done; es may alias B region now

        // Spill acc to smem [64][132]
        {
            const int tr = lane >> 2, tc2 = (lane & 3) * 2;
#pragma unroll
            for (int mi = 0; mi < 2; mi++) {
                int r = wr + mi * 16 + tr;
#pragma unroll
                for (int nj = 0; nj < 4; nj++) {
                    int col = wc + nj * 8 + tc2;
                    *(float2*)(es + r * 132 + col) =
                        make_float2(acc[mi][nj][0], acc[mi][nj][1]);
                    *(float2*)(es + (r + 8) * 132 + col) =
                        make_float2(acc[mi][nj][2], acc[mi][nj][3]);
                }
            }
        }
        __syncthreads();

        // Coalesced store with bias: 64 rows x 32 float4
        {
            const int c4 = tid & 31;
            const float* bias = Bptr[w];
            float4 b4 = *(const float4*)(bias + c4 * 4);
            float* dst = Dptr[w];
#pragma unroll
            for (int i = 0; i < 8; i++) {
                int r = (tid >> 5) + i * 8;
                int gr = row0 + r;
                if (gr < N_NODES) {
                    float4 v = *(const float4*)(es + r * 132 + c4 * 4);
                    v.x += b4.x; v.y += b4.y; v.z += b4.z; v.w += b4.w;
                    *(float4*)(dst + (size_t)gr * 128 + c4 * 4) = v;
                }
            }
        }
        __syncthreads();
    }
}

// ---------------------------------------------------------------------------
// Kernel 2: fused edge GEMM + epilogue, 64 edges per block.
// Two-loop fragment-shared mainloop (24 frag regs). Epilogue: 32 lanes per
// edge (1 edge/warp, 8 iterations) -> halved live state across RED sequences
// so __launch_bounds__(256,4) fits 64 regs without the R14 spills.
// ---------------------------------------------------------------------------
#define EF_AT (64 * ESTR * 2)            // 9216 B  (A: 64 rows)
#define EF_BT (128 * ESTR * 2)           // 18432 B (B: 128 rows)
#define EF_SMEM (2 * EF_AT + 2 * EF_BT)  // 55296 B; 4x = 216 KB fits SM

__global__ void __launch_bounds__(256, 4) k_edge(
    const float* __restrict__ ea,
    const int*   __restrict__ eidx)
{
    extern __shared__ char sm[];
    char* AHI = sm;                      char* ALO = sm + EF_AT;
    char* BHI = sm + 2 * EF_AT;          char* BLO = sm + 2 * EF_AT + EF_BT;
    const uint32_t sAhi = smem_u32(AHI), sAlo = smem_u32(ALO);
    const uint32_t sBhi = smem_u32(BHI), sBlo = smem_u32(BLO);
    float* es = (float*)sm;              // e tile [64][132] fp32 (aliases A/B)

    const int tid = threadIdx.x, wid = tid >> 5, lane = tid & 31;
    const int e0 = blockIdx.x * 64;
    const int wr = (wid & 1) * 32, wc = (wid >> 1) * 32;
    const int grp = lane >> 3;
    const int lr  = ((grp & 1) << 3) + (lane & 7);
    const int lk  = (grp >> 1) << 3;

    cvt_tile<64, 64, ESTR>(ea + (size_t)e0 * 64, N_EDGES - e0, AHI, ALO, tid);
    {
        const uint4* shi = (const uint4*)&g_WEhi[0];
        const uint4* slo = (const uint4*)&g_WElo[0];
        uint4* dhi = (uint4*)BHI;
        uint4* dlo = (uint4*)BLO;
        for (int t = tid; t < EF_BT / 16; t += 256) {
            dhi[t] = shi[t];
            dlo[t] = slo[t];
        }
    }
    __syncthreads();

    float acc[2][4][4];
#pragma unroll
    for (int mi = 0; mi < 2; mi++)
#pragma unroll
        for (int nj = 0; nj < 4; nj++)
#pragma unroll
            for (int q = 0; q < 4; q++) acc[mi][nj][q] = 0.f;

    // Loop A: A_hi x B_hi and A_hi x B_lo
#pragma unroll
    for (int k = 0; k < 64; k += 16) {
        uint32_t a[2][4], bh[2][4], bl[2][4];
#pragma unroll
        for (int mi = 0; mi < 2; mi++)
            LDSM4(a[mi], sAhi + ((wr + mi * 16 + lr) * ESTR + k + lk) * 2);
#pragma unroll
        for (int nt = 0; nt < 2; nt++) {
            LDSM4(bh[nt], sBhi + ((wc + nt * 16 + lr) * ESTR + k + lk) * 2);
            LDSM4(bl[nt], sBlo + ((wc + nt * 16 + lr) * ESTR + k + lk) * 2);
        }
#pragma unroll
        for (int mi = 0; mi < 2; mi++)
#pragma unroll
            for (int nt = 0; nt < 2; nt++) {
                MMA_BF16(acc[mi][nt * 2 + 0], a[mi], bh[nt][0], bh[nt][2]);
                MMA_BF16(acc[mi][nt * 2 + 1], a[mi], bh[nt][1], bh[nt][3]);
                MMA_BF16(acc[mi][nt * 2 + 0], a[mi], bl[nt][0], bl[nt][2]);
                MMA_BF16(acc[mi][nt * 2 + 1], a[mi], bl[nt][1], bl[nt][3]);
            }
    }
    // Loop B: A_lo x B_hi
#pragma unroll
    for (int k = 0; k < 64; k += 16) {
        uint32_t a[2][4], bh[2][4];
#pragma unroll
        for (int mi = 0; mi < 2; mi++)
            LDSM4(a[mi], sAlo + ((wr + mi * 16 + lr) * ESTR + k + lk) * 2);
#pragma unroll
        for (int nt = 0; nt < 2; nt++)
            LDSM4(bh[nt], sBhi + ((wc + nt * 16 + lr) * ESTR + k + lk) * 2);
#pragma unroll
        for (int mi = 0; mi < 2; mi++)
#pragma unroll
            for (int nt = 0; nt < 2; nt++) {
                MMA_BF16(acc[mi][nt * 2 + 0], a[mi], bh[nt][0], bh[nt][2]);
                MMA_BF16(acc[mi][nt * 2 + 1], a[mi], bh[nt][1], bh[nt][3]);
            }
    }
    __syncthreads();   // all warps done reading A/B; es may alias them now

    // Spill e tile to smem fp32 [64][132]
    {
        const int tr = lane >> 2, tc2 = (lane & 3) * 2;
#pragma unroll
        for (int mi = 0; mi < 2; mi++) {
            int r = wr + mi * 16 + tr;
#pragma unroll
            for (int nj = 0; nj < 4; nj++) {
                int col = wc + nj * 8 + tc2;
                *(float2*)(es + r * 132 + col) =
                    make_float2(acc[mi][nj][0], acc[mi][nj][1]);
                *(float2*)(es + (r + 8) * 132 + col) =
                    make_float2(acc[mi][nj][2], acc[mi][nj][3]);
            }
        }
    }
    __syncthreads();

    // Epilogue: 32 lanes per edge, 1 edge per warp, 8 iterations.
    // Lane li owns float4 at column li*4; head = li>>3. The 8-lane
    // shfl reduction leaves each group holding its own head's logit.
    const int c = lane * 4;
    const float sc = 0.17677669529663687f;  // 1/sqrt(32)

#pragma unroll
    for (int it = 0; it < 8; it++) {
        const int el = it * 8 + wid;
        const int ed = e0 + el;
        const bool valid = ed < N_EDGES;
        int s = 0, d = 0;
        if (valid) { s = eidx[ed]; d = eidx[N_EDGES + ed]; }

        float4 e4 = *(const float4*)(es + el * 132 + c);
        float4 v4 = make_float4(0.f, 0.f, 0.f, 0.f);
        float p = 0.f;
        if (valid) {
            float4 q4 = *(const float4*)(g_Q + (size_t)d * 128 + c);
            float4 k4 = *(const float4*)(g_K + (size_t)s * 128 + c);
            v4 = *(const float4*)(g_V + (size_t)s * 128 + c);
            p = q4.x * (k4.x + e4.x) + q4.y * (k4.y + e4.y) +
                q4.z * (k4.z + e4.z) + q4.w * (k4.w + e4.w);
        }
        // Reduce within the 8-lane head group -> per-head logit
        p += __shfl_xor_sync(0xffffffffu, p, 1);
        p += __shfl_xor_sync(0xffffffffu, p, 2);
        p += __shfl_xor_sync(0xffffffffu, p, 4);
        // Global max-shift cancels exactly in exp/denom; logits are O(3).
        float w = __expf(p * sc);

        if (valid && (lane & 7) == 0)
            atomicAdd(&g_D[(size_t)d * 4 + (lane >> 3)], w);
        if (valid) {
            float mx = (v4.x + e4.x) * w, my = (v4.y + e4.y) * w;
            float mz = (v4.z + e4.z) * w, mw = (v4.w + e4.w) * w;
            asm volatile("red.global.add.v4.f32 [%0], {%1,%2,%3,%4};"
                         :: "l"(g_ACC + (size_t)d * 128 + c),
                            "f"(mx), "f"(my), "f"(mz), "f"(mw)
                         : "memory");
        }
    }
}

// ---------------------------------------------------------------------------
// Kernel 3: out += g_ACC / (denom + 1e-16)   (skip already in out from k_proj)
// ---------------------------------------------------------------------------
__global__ void k_fin(float* __restrict__ out) {
    int i = blockIdx.x * blockDim.x + threadIdx.x;
    if (i < N_NODES * 32) {
        int n = i >> 5, q = i & 31, h = q >> 3;
        float inv = 1.f / (g_D[(size_t)n * 4 + h] + 1e-16f);
        float4 a = ((const float4*)g_ACC)[i];
        float4 o = ((float4*)out)[i];
        o.x += a.x * inv; o.y += a.y * inv;
        o.z += a.z * inv; o.w += a.w * inv;
        ((float4*)out)[i] = o;
    }
}

// ---------------------------------------------------------------------------
extern "C" void kernel_launch(void* const* d_in, const int* in_sizes, int n_in,
                              void* d_out, int out_size)
{
    const float* x    = (const float*)d_in[0];
    const int*   eidx = (const int*)  d_in[1];
    const float* ea   = (const float*)d_in[2];
    const float* Wq   = (const float*)d_in[3];
    const float* bq   = (const float*)d_in[4];
    const float* Wk   = (const float*)d_in[5];
    const float* bk   = (const float*)d_in[6];
    const float* Wv   = (const float*)d_in[7];
    const float* bv   = (const float*)d_in[8];
    const float* We   = (const float*)d_in[9];
    const float* Wsk  = (const float*)d_in[10];
    const float* bsk  = (const float*)d_in[11];
    float* out = (float*)d_out;

    cudaFuncSetAttribute(k_proj, cudaFuncAttributeMaxDynamicSharedMemorySize, PJ_SMEM);
    cudaFuncSetAttribute(k_edge, cudaFuncAttributeMaxDynamicSharedMemorySize, EF_SMEM);

    k_init<<<(N_NODES * 32 + 255) / 256, 256>>>(Wq, Wk, Wv, Wsk, We);
    k_proj<<<(N_NODES + 63) / 64, 256, PJ_SMEM>>>(x, bq, bk, bv, bsk, out);
    k_edge<<<(N_EDGES + 63) / 64, 256, EF_SMEM>>>(ea, eidx);
    k_fin<<<(N_NODES * 32 + 255) / 256, 256>>>(out);
}

// round 17
// speedup vs baseline: 1.1053x; 1.1053x over previous
#include <cuda_runtime.h>
#include <cuda_bf16.h>
#include <stdint.h>
#include <math.h>

#define N_NODES 100000
#define N_EDGES 500000

// Scratch (allocation-free rule: __device__ globals)
__device__ float g_Q[(size_t)N_NODES * 128];
__device__ float g_K[(size_t)N_NODES * 128];
__device__ float g_V[(size_t)N_NODES * 128];
__device__ float g_ACC[(size_t)N_NODES * 128];  // unnormalized message sums
__device__ float g_D[(size_t)N_NODES * 4];      // softmax denominators

#define PSTR 136   // proj smem row stride (bf16): 17x16B -> conflict-free LDSM
#define ESTR 72    // edge smem row stride (bf16): 9x16B  -> conflict-free LDSM

// Pre-converted weights (hi/lo bf16, pre-padded to smem strides)
__device__ __align__(16) __nv_bfloat16 g_Whi[4][128 * PSTR];
__device__ __align__(16) __nv_bfloat16 g_Wlo[4][128 * PSTR];
__device__ __align__(16) __nv_bfloat16 g_WEhi[128 * ESTR];
__device__ __align__(16) __nv_bfloat16 g_WElo[128 * ESTR];

// ---------------------------------------------------------------------------
// Portable tensor-core primitives (sm_80+; safe under the sm_103 family target)
// ---------------------------------------------------------------------------
__device__ __forceinline__ uint32_t smem_u32(const void* p) {
    uint32_t a;
    asm("{ .reg .u64 t; cvta.to.shared.u64 t, %1; cvt.u32.u64 %0, t; }"
        : "=r"(a) : "l"(p));
    return a;
}
#define LDSM4(r, addr) \
    asm volatile("ldmatrix.sync.aligned.m8n8.x4.shared.b16 {%0,%1,%2,%3}, [%4];" \
                 : "=r"((r)[0]), "=r"((r)[1]), "=r"((r)[2]), "=r"((r)[3]) \
                 : "r"(addr))
#define MMA_BF16(d, a, b0, b1) \
    asm volatile("mma.sync.aligned.m16n8k16.row.col.f32.bf16.bf16.f32 " \
                 "{%0,%1,%2,%3},{%4,%5,%6,%7},{%8,%9},{%0,%1,%2,%3};" \
                 : "+f"((d)[0]), "+f"((d)[1]), "+f"((d)[2]), "+f"((d)[3]) \
                 : "r"((a)[0]), "r"((a)[1]), "r"((a)[2]), "r"((a)[3]), \
                   "r"(b0), "r"(b1))

// ---------------------------------------------------------------------------
// fp32 -> bf16 hi/lo split into padded row-major smem (STR bf16 per row).
// ---------------------------------------------------------------------------
template <int ROWS, int KC, int STR>
__device__ __forceinline__ void cvt_tile(const float* __restrict__ src, int rows_valid,
                                         char* hi, char* lo, int tid) {
    const int QUADS = ROWS * (KC / 4);
    for (int t = tid; t < QUADS; t += 256) {
        int r = t / (KC / 4);
        int c = (t % (KC / 4)) * 4;
        float4 v = make_float4(0.f, 0.f, 0.f, 0.f);
        if (r < rows_valid) v = *(const float4*)(src + (size_t)r * KC + c);
        __nv_bfloat16 h0 = __float2bfloat16(v.x), h1 = __float2bfloat16(v.y);
        __nv_bfloat16 h2 = __float2bfloat16(v.z), h3 = __float2bfloat16(v.w);
        __nv_bfloat16 l0 = __float2bfloat16(v.x - __bfloat162float(h0));
        __nv_bfloat16 l1 = __float2bfloat16(v.y - __bfloat162float(h1));
        __nv_bfloat16 l2 = __float2bfloat16(v.z - __bfloat162float(h2));
        __nv_bfloat16 l3 = __float2bfloat16(v.w - __bfloat162float(h3));
        uint32_t off = (uint32_t)(r * STR + c) * 2;
        __nv_bfloat162 p;
        p.x = h0; p.y = h1; *(__nv_bfloat162*)(hi + off)     = p;
        p.x = h2; p.y = h3; *(__nv_bfloat162*)(hi + off + 4) = p;
        p.x = l0; p.y = l1; *(__nv_bfloat162*)(lo + off)     = p;
        p.x = l2; p.y = l3; *(__nv_bfloat162*)(lo + off + 4) = p;
    }
}

// ---------------------------------------------------------------------------
// Kernel 0: zero accumulators + one-time weight conversion (single launch)
// ---------------------------------------------------------------------------
__global__ void k_init(const float* __restrict__ Wq, const float* __restrict__ Wk,
                       const float* __restrict__ Wv, const float* __restrict__ Wsk,
                       const float* __restrict__ We) {
    int i = blockIdx.x * blockDim.x + threadIdx.x;
    if (i < N_NODES * 32) ((float4*)g_ACC)[i] = make_float4(0.f, 0.f, 0.f, 0.f);
    if (i < N_NODES)      ((float4*)g_D)[i]   = make_float4(0.f, 0.f, 0.f, 0.f);
    if (i < 4 * 16384) {
        int w = i >> 14, j = i & 16383, r = j >> 7, k = j & 127;
        const float* W = (w == 0) ? Wq : (w == 1) ? Wk : (w == 2) ? Wv : Wsk;
        float v = W[j];
        __nv_bfloat16 h = __float2bfloat16(v);
        __nv_bfloat16 l = __float2bfloat16(v - __bfloat162float(h));
        g_Whi[w][r * PSTR + k] = h;
        g_Wlo[w][r * PSTR + k] = l;
    } else if (i < 4 * 16384 + 8192) {
        int j = i - 4 * 16384, r = j >> 6, k = j & 63;
        float v = We[j];
        __nv_bfloat16 h = __float2bfloat16(v);
        __nv_bfloat16 l = __float2bfloat16(v - __bfloat162float(h));
        g_WEhi[r * ESTR + k] = h;
        g_WElo[r * ESTR + k] = l;
    }
}

// ---------------------------------------------------------------------------
// Kernel 1: node projections Q/K/V/skip. 64-row tile (2 CTAs/SM), 8 warps,
// each warp 32x32 via m16n8k16 bf16 HMMA. Fully-merged mainloop: all four
// fragment sets loaded once per k-step (8 LDSM4), 24 MMAs per step.
// ---------------------------------------------------------------------------
#define PJ_AT (64 * PSTR * 2)           // 17408 B
#define PJ_BT (128 * PSTR * 2)          // 34816 B
#define PJ_SMEM (2 * PJ_AT + 2 * PJ_BT) // 104448 B -> 2 CTAs/SM

__global__ void __launch_bounds__(256, 2) k_proj(
    const float* __restrict__ x,
    const float* __restrict__ bq, const float* __restrict__ bk,
    const float* __restrict__ bv, const float* __restrict__ bsk,
    float* __restrict__ out)
{
    extern __shared__ char sm[];
    char* AHI = sm;                     char* ALO = sm + PJ_AT;
    char* BHI = sm + 2 * PJ_AT;         char* BLO = sm + 2 * PJ_AT + PJ_BT;
    const uint32_t sAhi = smem_u32(AHI), sAlo = smem_u32(ALO);
    const uint32_t sBhi = smem_u32(BHI), sBlo = smem_u32(BLO);
    float* es = (float*)(sm + 2 * PJ_AT);  // [64][132] fp32 spill, aliases B

    const int tid = threadIdx.x, wid = tid >> 5, lane = tid & 31;
    const int row0 = blockIdx.x * 64;
    const int wr = (wid & 1) * 32, wc = (wid >> 1) * 32;

    const int grp = lane >> 3;
    const int lr  = ((grp & 1) << 3) + (lane & 7);
    const int lk  = (grp >> 1) << 3;

    cvt_tile<64, 128, PSTR>(x + (size_t)row0 * 128, N_NODES - row0, AHI, ALO, tid);

    const float* Bptr[4] = {bq, bk, bv, bsk};
    float*       Dptr[4] = {g_Q, g_K, g_V, out};

    for (int w = 0; w < 4; w++) {
        {
            const uint4* shi = (const uint4*)&g_Whi[w][0];
            const uint4* slo = (const uint4*)&g_Wlo[w][0];
            uint4* dhi = (uint4*)BHI;
            uint4* dlo = (uint4*)BLO;
            for (int t = tid; t < PJ_BT / 16; t += 256) {
                dhi[t] = shi[t];
                dlo[t] = slo[t];
            }
        }
        __syncthreads();

        float acc[2][4][4];
#pragma unroll
        for (int mi = 0; mi < 2; mi++)
#pragma unroll
            for (int nj = 0; nj < 4; nj++)
#pragma unroll
                for (int q = 0; q < 4; q++) acc[mi][nj][q] = 0.f;

        // Merged mainloop: 8 LDSM4 per k-step, 24 MMAs
#pragma unroll
        for (int k = 0; k < 128; k += 16) {
            uint32_t ah[2][4], al[2][4], bh[2][4], bl[2][4];
#pragma unroll
            for (int mi = 0; mi < 2; mi++) {
                LDSM4(ah[mi], sAhi + ((wr + mi * 16 + lr) * PSTR + k + lk) * 2);
                LDSM4(al[mi], sAlo + ((wr + mi * 16 + lr) * PSTR + k + lk) * 2);
            }
#pragma unroll
            for (int nt = 0; nt < 2; nt++) {
                LDSM4(bh[nt], sBhi + ((wc + nt * 16 + lr) * PSTR + k + lk) * 2);
                LDSM4(bl[nt], sBlo + ((wc + nt * 16 + lr) * PSTR + k + lk) * 2);
            }
#pragma unroll
            for (int mi = 0; mi < 2; mi++)
#pragma unroll
                for (int nt = 0; nt < 2; nt++) {
                    MMA_BF16(acc[mi][nt * 2 + 0], ah[mi], bh[nt][0], bh[nt][2]);
                    MMA_BF16(acc[mi][nt * 2 + 1], ah[mi], bh[nt][1], bh[nt][3]);
                    MMA_BF16(acc[mi][nt * 2 + 0], ah[mi], bl[nt][0], bl[nt][2]);
                    MMA_BF16(acc[mi][nt * 2 + 1], ah[mi], bl[nt][1], bl[nt][3]);
                    MMA_BF16(acc[mi][nt * 2 + 0], al[mi], bh[nt][0], bh[nt][2]);
                    MMA_BF16(acc[mi][nt * 2 + 1], al[mi], bh[nt][1], bh[nt][3]);
                }
        }
        __syncthreads();   // B reads done; es may alias B region now

        // Spill acc to smem [64][132]
        {
            const int tr = lane >> 2, tc2 = (lane & 3) * 2;
#pragma unroll
            for (int mi = 0; mi < 2; mi++) {
                int r = wr + mi * 16 + tr;
#pragma unroll
                for (int nj = 0; nj < 4; nj++) {
                    int col = wc + nj * 8 + tc2;
                    *(float2*)(es + r * 132 + col) =
                        make_float2(acc[mi][nj][0], acc[mi][nj][1]);
                    *(float2*)(es + (r + 8) * 132 + col) =
                        make_float2(acc[mi][nj][2], acc[mi][nj][3]);
                }
            }
        }
        __syncthreads();

        // Coalesced store with bias: 64 rows x 32 float4
        {
            const int c4 = tid & 31;
            const float* bias = Bptr[w];
            float4 b4 = *(const float4*)(bias + c4 * 4);
            float* dst = Dptr[w];
#pragma unroll
            for (int i = 0; i < 8; i++) {
                int r = (tid >> 5) + i * 8;
                int gr = row0 + r;
                if (gr < N_NODES) {
                    float4 v = *(const float4*)(es + r * 132 + c4 * 4);
                    v.x += b4.x; v.y += b4.y; v.z += b4.z; v.w += b4.w;
                    *(float4*)(dst + (size_t)gr * 128 + c4 * 4) = v;
                }
            }
        }
        __syncthreads();
    }
}

// ---------------------------------------------------------------------------
// Kernel 2: fused edge GEMM + epilogue, 64 edges per block (proven optimum:
// two-loop fragment-shared mainloop, 16-lane/edge epilogue,
// __launch_bounds__(256,3) -> 80 regs, 3 CTAs/SM, no spills).
// ---------------------------------------------------------------------------
#define EF_AT (64 * ESTR * 2)            // 9216 B  (A: 64 rows)
#define EF_BT (128 * ESTR * 2)           // 18432 B (B: 128 rows)
#define EF_SMEM (2 * EF_AT + 2 * EF_BT)  // 55296 B

__global__ void __launch_bounds__(256, 3) k_edge(
    const float* __restrict__ ea,
    const int*   __restrict__ eidx)
{
    extern __shared__ char sm[];
    char* AHI = sm;                      char* ALO = sm + EF_AT;
    char* BHI = sm + 2 * EF_AT;          char* BLO = sm + 2 * EF_AT + EF_BT;
    const uint32_t sAhi = smem_u32(AHI), sAlo = smem_u32(ALO);
    const uint32_t sBhi = smem_u32(BHI), sBlo = smem_u32(BLO);
    float* es = (float*)sm;              // e tile [64][132] fp32 (aliases A/B)

    const int tid = threadIdx.x, wid = tid >> 5, lane = tid & 31;
    const int e0 = blockIdx.x * 64;
    const int wr = (wid & 1) * 32, wc = (wid >> 1) * 32;
    const int grp = lane >> 3;
    const int lr  = ((grp & 1) << 3) + (lane & 7);
    const int lk  = (grp >> 1) << 3;

    cvt_tile<64, 64, ESTR>(ea + (size_t)e0 * 64, N_EDGES - e0, AHI, ALO, tid);
    {
        const uint4* shi = (const uint4*)&g_WEhi[0];
        const uint4* slo = (const uint4*)&g_WElo[0];
        uint4* dhi = (uint4*)BHI;
        uint4* dlo = (uint4*)BLO;
        for (int t = tid; t < EF_BT / 16; t += 256) {
            dhi[t] = shi[t];
            dlo[t] = slo[t];
        }
    }
    __syncthreads();

    float acc[2][4][4];
#pragma unroll
    for (int mi = 0; mi < 2; mi++)
#pragma unroll
        for (int nj = 0; nj < 4; nj++)
#pragma unroll
            for (int q = 0; q < 4; q++) acc[mi][nj][q] = 0.f;

    // Loop A: A_hi x B_hi and A_hi x B_lo
#pragma unroll
    for (int k = 0; k < 64; k += 16) {
        uint32_t a[2][4], bh[2][4], bl[2][4];
#pragma unroll
        for (int mi = 0; mi < 2; mi++)
            LDSM4(a[mi], sAhi + ((wr + mi * 16 + lr) * ESTR + k + lk) * 2);
#pragma unroll
        for (int nt = 0; nt < 2; nt++) {
            LDSM4(bh[nt], sBhi + ((wc + nt * 16 + lr) * ESTR + k + lk) * 2);
            LDSM4(bl[nt], sBlo + ((wc + nt * 16 + lr) * ESTR + k + lk) * 2);
        }
#pragma unroll
        for (int mi = 0; mi < 2; mi++)
#pragma unroll
            for (int nt = 0; nt < 2; nt++) {
                MMA_BF16(acc[mi][nt * 2 + 0], a[mi], bh[nt][0], bh[nt][2]);
                MMA_BF16(acc[mi][nt * 2 + 1], a[mi], bh[nt][1], bh[nt][3]);
                MMA_BF16(acc[mi][nt * 2 + 0], a[mi], bl[nt][0], bl[nt][2]);
                MMA_BF16(acc[mi][nt * 2 + 1], a[mi], bl[nt][1], bl[nt][3]);
            }
    }
    // Loop B: A_lo x B_hi
#pragma unroll
    for (int k = 0; k < 64; k += 16) {
        uint32_t a[2][4], bh[2][4];
#pragma unroll
        for (int mi = 0; mi < 2; mi++)
            LDSM4(a[mi], sAlo + ((wr + mi * 16 + lr) * ESTR + k + lk) * 2);
#pragma unroll
        for (int nt = 0; nt < 2; nt++)
            LDSM4(bh[nt], sBhi + ((wc + nt * 16 + lr) * ESTR + k + lk) * 2);
#pragma unroll
        for (int mi = 0; mi < 2; mi++)
#pragma unroll
            for (int nt = 0; nt < 2; nt++) {
                MMA_BF16(acc[mi][nt * 2 + 0], a[mi], bh[nt][0], bh[nt][2]);
                MMA_BF16(acc[mi][nt * 2 + 1], a[mi], bh[nt][1], bh[nt][3]);
            }
    }
    __syncthreads();   // all warps done reading A/B; es may alias them now

    // Spill e tile to smem fp32 [64][132]
    {
        const int tr = lane >> 2, tc2 = (lane & 3) * 2;
#pragma unroll
        for (int mi = 0; mi < 2; mi++) {
            int r = wr + mi * 16 + tr;
#pragma unroll
            for (int nj = 0; nj < 4; nj++) {
                int col = wc + nj * 8 + tc2;
                *(float2*)(es + r * 132 + col) =
                    make_float2(acc[mi][nj][0], acc[mi][nj][1]);
                *(float2*)(es + (r + 8) * 132 + col) =
                    make_float2(acc[mi][nj][2], acc[mi][nj][3]);
            }
        }
    }
    __syncthreads();

    // Epilogue: 16 lanes per edge, 2 edges per warp, 4 iterations.
    const int sub = lane >> 4;   // edge within warp
    const int li  = lane & 15;
    const int c0 = li * 4, c1 = 64 + li * 4;
    const float sc = 0.17677669529663687f;  // 1/sqrt(32)

#pragma unroll
    for (int it = 0; it < 4; it++) {
        const int el = it * 16 + wid * 2 + sub;
        const int ed = e0 + el;
        const bool valid = ed < N_EDGES;
        int s = 0, d = 0;
        if (valid) { s = eidx[ed]; d = eidx[N_EDGES + ed]; }

        float4 e4[2], v4[2];
        float p[2] = {0.f, 0.f};
        e4[0] = *(const float4*)(es + el * 132 + c0);
        e4[1] = *(const float4*)(es + el * 132 + c1);
        if (valid) {
            const float* Qr = g_Q + (size_t)d * 128;
            const float* Kr = g_K + (size_t)s * 128;
            const float* Vr = g_V + (size_t)s * 128;
#pragma unroll
            for (int j = 0; j < 2; j++) {
                int c = j ? c1 : c0;
                float4 q4 = *(const float4*)(Qr + c);
                float4 k4 = *(const float4*)(Kr + c);
                v4[j] = *(const float4*)(Vr + c);
                p[j] = q4.x * (k4.x + e4[j].x) + q4.y * (k4.y + e4[j].y) +
                       q4.z * (k4.z + e4[j].z) + q4.w * (k4.w + e4[j].w);
            }
        }
        // Reduce within each 8-lane head group
#pragma unroll
        for (int off = 1; off < 8; off <<= 1) {
            p[0] += __shfl_xor_sync(0xffffffffu, p[0], off);
            p[1] += __shfl_xor_sync(0xffffffffu, p[1], off);
        }
        // Global max-shift cancels exactly in exp/denom; logits are O(3).
        float w0 = __expf(p[0] * sc);
        float w1 = __expf(p[1] * sc);

        if (valid && (li & 7) == 0) {
            int hb = li >> 3;
            atomicAdd(&g_D[(size_t)d * 4 + hb], w0);
            atomicAdd(&g_D[(size_t)d * 4 + 2 + hb], w1);
        }
        if (valid) {
            float* ap = g_ACC + (size_t)d * 128;
            float mx = (v4[0].x + e4[0].x) * w0, my = (v4[0].y + e4[0].y) * w0;
            float mz = (v4[0].z + e4[0].z) * w0, mw = (v4[0].w + e4[0].w) * w0;
            asm volatile("red.global.add.v4.f32 [%0], {%1,%2,%3,%4};"
                         :: "l"(ap + c0), "f"(mx), "f"(my), "f"(mz), "f"(mw)
                         : "memory");
            mx = (v4[1].x + e4[1].x) * w1; my = (v4[1].y + e4[1].y) * w1;
            mz = (v4[1].z + e4[1].z) * w1; mw = (v4[1].w + e4[1].w) * w1;
            asm volatile("red.global.add.v4.f32 [%0], {%1,%2,%3,%4};"
                         :: "l"(ap + c1), "f"(mx), "f"(my), "f"(mz), "f"(mw)
                         : "memory");
        }
    }
}

// ---------------------------------------------------------------------------
// Kernel 3: out += g_ACC / (denom + 1e-16)   (skip already in out from k_proj)
// ---------------------------------------------------------------------------
__global__ void k_fin(float* __restrict__ out) {
    int i = blockIdx.x * blockDim.x + threadIdx.x;
    if (i < N_NODES * 32) {
        int n = i >> 5, q = i & 31, h = q >> 3;
        float inv = 1.f / (g_D[(size_t)n * 4 + h] + 1e-16f);
        float4 a = ((const float4*)g_ACC)[i];
        float4 o = ((float4*)out)[i];
        o.x += a.x * inv; o.y += a.y * inv;
        o.z += a.z * inv; o.w += a.w * inv;
        ((float4*)out)[i] = o;
    }
}

// ---------------------------------------------------------------------------
extern "C" void kernel_launch(void* const* d_in, const int* in_sizes, int n_in,
                              void* d_out, int out_size)
{
    const float* x    = (const float*)d_in[0];
    const int*   eidx = (const int*)  d_in[1];
    const float* ea   = (const float*)d_in[2];
    const float* Wq   = (const float*)d_in[3];
    const float* bq   = (const float*)d_in[4];
    const float* Wk   = (const float*)d_in[5];
    const float* bk   = (const float*)d_in[6];
    const float* Wv   = (const float*)d_in[7];
    const float* bv   = (const float*)d_in[8];
    const float* We   = (const float*)d_in[9];
    const float* Wsk  = (const float*)d_in[10];
    const float* bsk  = (const float*)d_in[11];
    float* out = (float*)d_out;

    cudaFuncSetAttribute(k_proj, cudaFuncAttributeMaxDynamicSharedMemorySize, PJ_SMEM);
    cudaFuncSetAttribute(k_edge, cudaFuncAttributeMaxDynamicSharedMemorySize, EF_SMEM);

    k_init<<<(N_NODES * 32 + 255) / 256, 256>>>(Wq, Wk, Wv, Wsk, We);
    k_proj<<<(N_NODES + 63) / 64, 256, PJ_SMEM>>>(x, bq, bk, bv, bsk, out);
    k_edge<<<(N_EDGES + 63) / 64, 256, EF_SMEM>>>(ea, eidx);
    k_fin<<<(N_NODES * 32 + 255) / 256, 256>>>(out);
}